// round 13
// baseline (speedup 1.0000x reference)
#include <cuda_runtime.h>
#include <cstdint>

// ---------------------------------------------------------------------------
// Problem constants
// ---------------------------------------------------------------------------
#define B_       16
#define M_       100
#define HW_TOT   21824          // 128^2 + 64^2 + 32^2 + 16^2 + 8^2
#define NPIX     (B_ * HW_TOT)

#define CLS_N    (NPIX * 82)
#define REG_N    (NPIX * 6)
#define OFF_REG  ((size_t)CLS_N)
#define OFF_IND  (OFF_REG + REG_N)
#define OFF_NB   (OFF_IND + NPIX)

// 64-pixel slabs; 341 per batch (21824 = 341*64), all level bounds 64-aligned.
#define SLAB         64
#define NSLAB_PER_B  341
#define NSLAB        (NSLAB_PER_B * B_)     // 5456

// per-buffer smem layout (bytes): [cls][reg][ind]
#define BUF_CLS_BYTES (SLAB * 82 * 4)       // 20992
#define BUF_REG_OFF   BUF_CLS_BYTES
#define BUF_REG_BYTES (SLAB * 6 * 4)        // 1536
#define BUF_IND_OFF   (BUF_REG_OFF + BUF_REG_BYTES)
#define BUF_IND_BYTES (SLAB * 4)            // 256
#define BUF_BYTES     (BUF_IND_OFF + BUF_IND_BYTES)   // 22784
#define SM_TOTAL      (2 * BUF_BYTES)       // 45568

#define GRID_X   592                        // 4 CTAs/SM * 148 SMs, one wave

__device__ __constant__ int   c_off[5]   = {0, 16384, 20480, 21504, 21760};
__device__ __constant__ int   c_shift[5] = {7, 6, 5, 4, 3};
__device__ __constant__ float c_stride[5]= {8.f, 16.f, 32.f, 64.f, 128.f};

// ---------------------------------------------------------------------------
// Persistent double-buffered TMA-store kernel. grid=592, block=128.
// Each CTA grid-strides over 64-pixel slabs. Per slab:
//   wait_group 1 (buffer from 2 iters ago drained) -> compute into buf[i&1]
//   -> fence + 3 cp.async.bulk + commit_group.
// The TMA drain of slab i overlaps the compute of slab i+1.
// ---------------------------------------------------------------------------
__global__ __launch_bounds__(128) void fused_kernel(const float* __restrict__ gt,
                                                    float* __restrict__ out)
{
    extern __shared__ __align__(16) unsigned char dyn[];

    __shared__ float4 cbnd[M_];    // candidate shrunk bounds (level coords)
    __shared__ float4 cbox[M_];    // candidate image-space box
    __shared__ float  carea[M_];
    __shared__ int    cj[M_];
    __shared__ int    clab[M_];
    __shared__ int    s_cnt;

    const int t = threadIdx.x;

    uint32_t s_base;
    asm("{ .reg .u64 tmp; cvta.to.shared.u64 tmp, %1; cvt.u32.u64 %0, tmp; }"
        : "=r"(s_base) : "l"(dyn));

    int iter = 0;
    for (int s = blockIdx.x; s < NSLAB; s += GRID_X, ++iter) {
        const int      bufsel = iter & 1;
        unsigned char* bufp   = dyn + bufsel * BUF_BYTES;
        float* sm_cls = reinterpret_cast<float*>(bufp);
        float* sm_reg = reinterpret_cast<float*>(bufp + BUF_REG_OFF);
        float* sm_ind = reinterpret_cast<float*>(bufp + BUF_IND_OFF);

        // Reclaim the buffer committed 2 iterations ago; reset candidate count.
        if (t == 0) {
            asm volatile("cp.async.bulk.wait_group 1;" ::: "memory");
            s_cnt = 0;
        }
        __syncthreads();

        const int b  = s / NSLAB_PER_B;
        const int sl = s - b * NSLAB_PER_B;
        const int p0 = sl * SLAB;

        int lev;
        if      (p0 < 16384) lev = 0;
        else if (p0 < 20480) lev = 1;
        else if (p0 < 21504) lev = 2;
        else if (p0 < 21760) lev = 3;
        else                 lev = 4;

        const int   sh  = c_shift[lev];
        const int   fw  = 1 << sh;
        const float fS  = c_stride[lev];
        const float inv = 1.0f / fS;             // exact (power of two)
        const int   off = c_off[lev];
        const int   g0  = b * HW_TOT + p0;

        const int local0 = p0 - off;
        const int by0 = local0 >> sh;
        const int by1 = (local0 + SLAB - 1) >> sh;

        // ---- Phase A: candidate build ----
        int validp = 0;
        if (t < M_) {
            const float* bp = gt + (b * M_ + t) * 5;
            float x1 = bp[0], y1 = bp[1], x2 = bp[2], y2 = bp[3];

            float b0 = x1 * inv, b1 = y1 * inv, b2 = x2 * inv, b3 = y2 * inv;
            float cx = (b0 + b2) * 0.5f;
            float cy = (b1 + b3) * 0.5f;
            float hw = (b2 - b0) * 0.5f * 0.2f;
            float hh = (b3 - b1) * 0.5f * 0.2f;
            float px1 = fmaxf(floorf(cx - hw), 0.0f);
            float py1 = fmaxf(floorf(cy - hh), 0.0f);
            float px2 = fminf(ceilf(cx + hw), (float)fw);
            float py2 = fminf(ceilf(cy + hh), (float)fw);

            bool hit = (px2 > px1) && (py2 > py1) &&
                       (py1 <= (float)by1) && (py2 > (float)by0);
            if (hit) {
                int k = atomicAdd(&s_cnt, 1);
                cbnd[k]  = make_float4(px1, py1, px2, py2);
                cbox[k]  = make_float4(x1, y1, x2, y2);
                carea[k] = (x2 - x1) * (y2 - y1);
                cj[k]    = t;
                clab[k]  = (int)bp[4];
            }
            validp = (fabsf(x1) + fabsf(y1) + fabsf(x2) + fabsf(y2) > 0.0f) ? 1 : 0;
        }
        int nvalid = __syncthreads_count(validp);

        if (sl == NSLAB_PER_B - 1 && t == 0)
            out[OFF_NB + b] = (float)nvalid;

        // ---- Phase B: per-pixel argmin; build outputs in smem (t < 64) ----
        if (t < SLAB) {
            const int   p     = p0 + t;
            const int   local = p - off;
            const int   y     = local >> sh;
            const int   x     = local & (fw - 1);
            const float fx    = (float)x;
            const float fy    = (float)y;

            const int cnt = s_cnt;
            float bestA = 1e7f;
            int   bestK = -1, bestJ = -1;
            for (int k = 0; k < cnt; k++) {
                float4 bb = cbnd[k];
                bool inside = (fx >= bb.x) & (fx < bb.z) & (fy >= bb.y) & (fy < bb.w);
                float a = carea[k];
                int   j = cj[k];
                if (inside && (a < bestA || (a == bestA && j < bestJ))) {
                    bestA = a; bestJ = j; bestK = k;
                }
            }

            float soft = 1.0f, posf = 0.0f;
            float4 rg = make_float4(0.f, 0.f, 0.f, 0.f);
            int    lab = -1;
            if (bestK >= 0) {
                float4 wb = cbox[bestK];
                float sx = (fx + 0.5f) * fS;
                float sy = (fy + 0.5f) * fS;
                float l  = sx - wb.x;
                float tt = sy - wb.y;
                float r  = wb.z - sx;
                float bt = wb.w - sy;
                const float eps = 1e-6f;
                float q1 = fminf(fmaxf(fminf(l, r)  / fmaxf(fmaxf(l, r),  eps), 0.f), 1.f);
                float q2 = fminf(fmaxf(fminf(tt, bt)/ fmaxf(fmaxf(tt, bt), eps), 0.f), 1.f);
                soft = sqrtf(q1 * q2);
                posf = 1.0f;
                lab  = clab[bestK];
                float inv4 = 0.25f * inv;         // 1/(4*stride), exact
                rg = make_float4(l * inv4, tt * inv4, r * inv4, bt * inv4);
            }

            // cls row: 41 float2 stores (slot 40 = {soft,posf}) + one-hot patch
            float2* row2 = reinterpret_cast<float2*>(sm_cls + t * 82);
            const float2 z2 = make_float2(0.f, 0.f);
#pragma unroll
            for (int i = 0; i < 40; i++) row2[i] = z2;
            row2[40] = make_float2(soft, posf);
            if (lab >= 0) (sm_cls + t * 82)[lab] = 1.0f;

            float2* rp = reinterpret_cast<float2*>(sm_reg + t * 6);
            rp[0] = make_float2(rg.x, rg.y);
            rp[1] = make_float2(rg.z, rg.w);
            rp[2] = make_float2(soft, posf);

            sm_ind[t] = (bestK >= 0) ? (float)bestJ : -1.0f;
        }
        __syncthreads();

        // ---- Phase C: bulk async stores smem -> gmem (thread 0), no wait ----
        if (t == 0) {
            asm volatile("fence.proxy.async.shared::cta;" ::: "memory");

            const uint32_t sb = s_base + bufsel * BUF_BYTES;
            const float* g_cls = out + (size_t)g0 * 82;
            const float* g_reg = out + OFF_REG + (size_t)g0 * 6;
            const float* g_ind = out + OFF_IND + g0;

            asm volatile("cp.async.bulk.global.shared::cta.bulk_group [%0], [%1], %2;"
                         :: "l"(g_cls), "r"(sb), "n"(SLAB * 82 * 4) : "memory");
            asm volatile("cp.async.bulk.global.shared::cta.bulk_group [%0], [%1], %2;"
                         :: "l"(g_reg), "r"(sb + BUF_REG_OFF), "n"(SLAB * 6 * 4) : "memory");
            asm volatile("cp.async.bulk.global.shared::cta.bulk_group [%0], [%1], %2;"
                         :: "l"(g_ind), "r"(sb + BUF_IND_OFF), "n"(SLAB * 4) : "memory");
            asm volatile("cp.async.bulk.commit_group;" ::: "memory");
        }
    }

    // Drain all outstanding bulk stores before the CTA releases its smem.
    if (t == 0)
        asm volatile("cp.async.bulk.wait_group 0;" ::: "memory");
}

// ---------------------------------------------------------------------------
extern "C" void kernel_launch(void* const* d_in, const int* in_sizes, int n_in,
                              void* d_out, int out_size)
{
    const float* gt  = (const float*)d_in[0];
    float*       out = (float*)d_out;

    static int configured = 0;
    if (!configured) {
        cudaFuncSetAttribute(fused_kernel,
                             cudaFuncAttributeMaxDynamicSharedMemorySize, SM_TOTAL);
        configured = 1;
    }

    fused_kernel<<<GRID_X, 128, SM_TOTAL>>>(gt, out);
}

// round 14
// speedup vs baseline: 1.0803x; 1.0803x over previous
#include <cuda_runtime.h>
#include <cstdint>

// ---------------------------------------------------------------------------
// Problem constants
// ---------------------------------------------------------------------------
#define B_       16
#define M_       100
#define HW_TOT   21824          // 128^2 + 64^2 + 32^2 + 16^2 + 8^2
#define NPIX     (B_ * HW_TOT)

#define CLS_N    (NPIX * 82)
#define REG_N    (NPIX * 6)
#define OFF_REG  ((size_t)CLS_N)
#define OFF_IND  (OFF_REG + REG_N)
#define OFF_NB   (OFF_IND + NPIX)

// 64-pixel slabs; 341 per batch (21824 = 341*64), all level bounds 64-aligned.
#define SLAB     64
#define NSLAB_X  341

// dynamic smem layout (bytes): [cls][reg][ind]
#define SM_CLS_BYTES (SLAB * 82 * 4)     // 20992
#define SM_REG_OFF   SM_CLS_BYTES
#define SM_REG_BYTES (SLAB * 6 * 4)      // 1536
#define SM_IND_OFF   (SM_REG_OFF + SM_REG_BYTES)
#define SM_IND_BYTES (SLAB * 4)          // 256
#define SM_TOTAL     (SM_IND_OFF + SM_IND_BYTES)   // 22784

__device__ __constant__ int   c_off[5]   = {0, 16384, 20480, 21504, 21760};
__device__ __constant__ int   c_shift[5] = {7, 6, 5, 4, 3};
__device__ __constant__ float c_stride[5]= {8.f, 16.f, 32.f, 64.f, 128.f};

// ---------------------------------------------------------------------------
// TMA-store version, 8-deep pipeline. grid=(341,16), block=128.
// 64-pixel single-level slabs (bounds at slab 256/320/336/340).
//   A: per-block candidate compaction (threads < M_).
//   B: per-pixel argmin (t < 64); thread t builds its own outputs in smem:
//      cls row = 41 STS.64 (slot 40 = {soft,posf}) + one-hot STS.32 patch,
//      reg record = 3 STS.64, ind = 1 STS.32.
//   C: thread 0 issues 3 cp.async.bulk smem->gmem copies and waits.
// ---------------------------------------------------------------------------
__global__ __launch_bounds__(128) void fused_kernel(const float* __restrict__ gt,
                                                    float* __restrict__ out)
{
    extern __shared__ __align__(16) unsigned char dyn[];
    float* sm_cls = reinterpret_cast<float*>(dyn);
    float* sm_reg = reinterpret_cast<float*>(dyn + SM_REG_OFF);
    float* sm_ind = reinterpret_cast<float*>(dyn + SM_IND_OFF);

    __shared__ float4 cbnd[M_];    // candidate shrunk bounds (level coords)
    __shared__ float4 cbox[M_];    // candidate image-space box
    __shared__ float  carea[M_];
    __shared__ int    cj[M_];
    __shared__ int    clab[M_];
    __shared__ int    s_cnt;

    const int b  = blockIdx.y;
    const int bx = blockIdx.x;
    const int p0 = bx * SLAB;
    const int t  = threadIdx.x;

    int lev;
    if      (bx < 256) lev = 0;
    else if (bx < 320) lev = 1;
    else if (bx < 336) lev = 2;
    else if (bx < 340) lev = 3;
    else               lev = 4;

    const int   sh  = c_shift[lev];
    const int   fw  = 1 << sh;
    const float fS  = c_stride[lev];
    const float inv = 1.0f / fS;                 // exact (power of two)
    const int   off = c_off[lev];
    const int   g0  = b * HW_TOT + p0;

    const int local0 = p0 - off;
    const int by0 = local0 >> sh;
    const int by1 = (local0 + SLAB - 1) >> sh;

    if (t == 0) s_cnt = 0;
    __syncthreads();

    // ---- Phase A: candidate build ----
    int validp = 0;
    if (t < M_) {
        const float* bp = gt + (b * M_ + t) * 5;
        float x1 = bp[0], y1 = bp[1], x2 = bp[2], y2 = bp[3];

        float b0 = x1 * inv, b1 = y1 * inv, b2 = x2 * inv, b3 = y2 * inv;
        float cx = (b0 + b2) * 0.5f;
        float cy = (b1 + b3) * 0.5f;
        float hw = (b2 - b0) * 0.5f * 0.2f;
        float hh = (b3 - b1) * 0.5f * 0.2f;
        float px1 = fmaxf(floorf(cx - hw), 0.0f);
        float py1 = fmaxf(floorf(cy - hh), 0.0f);
        float px2 = fminf(ceilf(cx + hw), (float)fw);
        float py2 = fminf(ceilf(cy + hh), (float)fw);

        bool hit = (px2 > px1) && (py2 > py1) &&
                   (py1 <= (float)by1) && (py2 > (float)by0);
        if (hit) {
            int k = atomicAdd(&s_cnt, 1);
            cbnd[k]  = make_float4(px1, py1, px2, py2);
            cbox[k]  = make_float4(x1, y1, x2, y2);
            carea[k] = (x2 - x1) * (y2 - y1);
            cj[k]    = t;
            clab[k]  = (int)bp[4];
        }
        validp = (fabsf(x1) + fabsf(y1) + fabsf(x2) + fabsf(y2) > 0.0f) ? 1 : 0;
    }
    int nvalid = __syncthreads_count(validp);

    if (bx == 340 && t == 0)
        out[OFF_NB + b] = (float)nvalid;

    // ---- Phase B: per-pixel argmin; build outputs in smem (t < 64) ----
    if (t < SLAB) {
        const int   p     = p0 + t;
        const int   local = p - off;
        const int   y     = local >> sh;
        const int   x     = local & (fw - 1);
        const float fx    = (float)x;
        const float fy    = (float)y;

        const int cnt = s_cnt;
        float bestA = 1e7f;
        int   bestK = -1, bestJ = -1;
        for (int k = 0; k < cnt; k++) {
            float4 bb = cbnd[k];
            bool inside = (fx >= bb.x) & (fx < bb.z) & (fy >= bb.y) & (fy < bb.w);
            float a = carea[k];
            int   j = cj[k];
            if (inside && (a < bestA || (a == bestA && j < bestJ))) {
                bestA = a; bestJ = j; bestK = k;
            }
        }

        float soft = 1.0f, posf = 0.0f;
        float4 rg = make_float4(0.f, 0.f, 0.f, 0.f);
        int    lab = -1;
        if (bestK >= 0) {
            float4 wb = cbox[bestK];
            float sx = (fx + 0.5f) * fS;
            float sy = (fy + 0.5f) * fS;
            float l  = sx - wb.x;
            float tt = sy - wb.y;
            float r  = wb.z - sx;
            float bt = wb.w - sy;
            const float eps = 1e-6f;
            float q1 = fminf(fmaxf(fminf(l, r)  / fmaxf(fmaxf(l, r),  eps), 0.f), 1.f);
            float q2 = fminf(fmaxf(fminf(tt, bt)/ fmaxf(fmaxf(tt, bt), eps), 0.f), 1.f);
            soft = sqrtf(q1 * q2);
            posf = 1.0f;
            lab  = clab[bestK];
            float inv4 = 0.25f * inv;             // 1/(4*stride), exact
            rg = make_float4(l * inv4, tt * inv4, r * inv4, bt * inv4);
        }

        // cls row: 41 float2 stores (slot 40 = {soft,posf}), then one-hot patch
        float2* row2 = reinterpret_cast<float2*>(sm_cls + t * 82);
        const float2 z2 = make_float2(0.f, 0.f);
#pragma unroll
        for (int i = 0; i < 40; i++) row2[i] = z2;
        row2[40] = make_float2(soft, posf);
        if (lab >= 0) (sm_cls + t * 82)[lab] = 1.0f;

        // reg record: 3 float2 stores
        float2* rp = reinterpret_cast<float2*>(sm_reg + t * 6);
        rp[0] = make_float2(rg.x, rg.y);
        rp[1] = make_float2(rg.z, rg.w);
        rp[2] = make_float2(soft, posf);

        sm_ind[t] = (bestK >= 0) ? (float)bestJ : -1.0f;
    }
    __syncthreads();

    // ---- Phase C: bulk async stores smem -> gmem (thread 0) ----
    if (t == 0) {
        asm volatile("fence.proxy.async.shared::cta;" ::: "memory");

        uint32_t s_base;
        asm("{ .reg .u64 tmp; cvta.to.shared.u64 tmp, %1; cvt.u32.u64 %0, tmp; }"
            : "=r"(s_base) : "l"(dyn));

        const float* g_cls = out + (size_t)g0 * 82;
        const float* g_reg = out + OFF_REG + (size_t)g0 * 6;
        const float* g_ind = out + OFF_IND + g0;

        asm volatile("cp.async.bulk.global.shared::cta.bulk_group [%0], [%1], %2;"
                     :: "l"(g_cls), "r"(s_base), "n"(SLAB * 82 * 4) : "memory");
        asm volatile("cp.async.bulk.global.shared::cta.bulk_group [%0], [%1], %2;"
                     :: "l"(g_reg), "r"(s_base + SM_REG_OFF), "n"(SLAB * 6 * 4) : "memory");
        asm volatile("cp.async.bulk.global.shared::cta.bulk_group [%0], [%1], %2;"
                     :: "l"(g_ind), "r"(s_base + SM_IND_OFF), "n"(SLAB * 4) : "memory");
        asm volatile("cp.async.bulk.commit_group;" ::: "memory");
        asm volatile("cp.async.bulk.wait_group 0;" ::: "memory");
    }
}

// ---------------------------------------------------------------------------
extern "C" void kernel_launch(void* const* d_in, const int* in_sizes, int n_in,
                              void* d_out, int out_size)
{
    const float* gt  = (const float*)d_in[0];
    float*       out = (float*)d_out;

    static int configured = 0;
    if (!configured) {
        cudaFuncSetAttribute(fused_kernel,
                             cudaFuncAttributeMaxDynamicSharedMemorySize, SM_TOTAL);
        configured = 1;
    }

    dim3 grid(NSLAB_X, B_);                       // (341, 16)
    fused_kernel<<<grid, 128, SM_TOTAL>>>(gt, out);
}